// round 3
// baseline (speedup 1.0000x reference)
#include <cuda_runtime.h>
#include <math.h>

// Problem constants
#define SEQ   2048
#define HID   1024
#define NHEAD 16
#define DHEAD 64
#define ATT_SCALE 0.125f   // 1/sqrt(64)

// ---------------- scratch (__device__ globals; no allocations allowed) ----------------
__device__ float g_q[SEQ * HID];
__device__ float g_k[SEQ * HID];
__device__ float g_v[SEQ * HID];
__device__ float g_ctx[SEQ * HID];
__device__ float g_out[SEQ * HID];
__device__ float g_rq[SEQ * HID];
__device__ float g_rk[SEQ * HID];
__device__ float g_rv[SEQ * HID];
__device__ float g_rctx0[SEQ * HID];
__device__ float g_rctx1[SEQ * HID];
__device__ float g_rec[SEQ * HID];
__device__ float g_gate[SEQ * HID];
__device__ float g_scores[(size_t)NHEAD * SEQ * SEQ];   // 256 MB, reused per attention pass

// ---------------- generic tiled fp32 GEMM ----------------
// C[m][n] = alpha * sum_k A[m][k] * (TB ? B[n][k] : B[k][n])  (+bias[n]) (+=C if accum)
// Batched via blockIdx.z with element strides sA/sB/sC.
#define BM 128
#define BN 64
#define BK 16
#define TM 8
#define TN 4

template <bool TB>
__global__ __launch_bounds__(256, 2)
void gemm_kernel(const float* __restrict__ A, int lda, long long sA,
                 const float* __restrict__ B, int ldb, long long sB,
                 const float* __restrict__ bias,
                 float* __restrict__ C, int ldc, long long sC,
                 int M, int N, int K, float alpha, int accum)
{
    __shared__ float As[BK][BM + 1];
    __shared__ float Bs[BK][BN + 1];

    const int tid = threadIdx.x;
    const int tx = tid & 15;        // 0..15 -> TN columns each
    const int ty = tid >> 4;        // 0..15 -> TM rows each
    const int row0 = blockIdx.y * BM;
    const int col0 = blockIdx.x * BN;
    const long long zb = blockIdx.z;

    const float* Ab = A + zb * sA;
    const float* Bb = B + zb * sB;
    float* Cb = C + zb * sC;

    float acc[TM][TN];
#pragma unroll
    for (int i = 0; i < TM; i++)
#pragma unroll
        for (int j = 0; j < TN; j++) acc[i][j] = 0.0f;

    for (int k0 = 0; k0 < K; k0 += BK) {
        // Load A tile: 128x16 = 2048 elems, 8 per thread
#pragma unroll
        for (int i = 0; i < 8; i++) {
            int idx = tid + i * 256;
            int m = idx >> 4, kk = idx & 15;
            As[kk][m] = Ab[(long long)(row0 + m) * lda + (k0 + kk)];
        }
        // Load B tile: 16x64 = 1024 elems, 4 per thread
#pragma unroll
        for (int i = 0; i < 4; i++) {
            int idx = tid + i * 256;
            if (TB) {
                int n = idx >> 4, kk = idx & 15;
                Bs[kk][n] = Bb[(long long)(col0 + n) * ldb + (k0 + kk)];
            } else {
                int kk = idx >> 6, n = idx & 63;
                Bs[kk][n] = Bb[(long long)(k0 + kk) * ldb + (col0 + n)];
            }
        }
        __syncthreads();

#pragma unroll
        for (int kk = 0; kk < BK; kk++) {
            float a[TM], b[TN];
#pragma unroll
            for (int i = 0; i < TM; i++) a[i] = As[kk][ty * TM + i];
#pragma unroll
            for (int j = 0; j < TN; j++) b[j] = Bs[kk][tx * TN + j];
#pragma unroll
            for (int i = 0; i < TM; i++)
#pragma unroll
                for (int j = 0; j < TN; j++) acc[i][j] += a[i] * b[j];
        }
        __syncthreads();
    }

#pragma unroll
    for (int i = 0; i < TM; i++) {
        int m = row0 + ty * TM + i;
#pragma unroll
        for (int j = 0; j < TN; j++) {
            int n = col0 + tx * TN + j;
            float v = acc[i][j] * alpha;
            if (bias) v += bias[n];
            long long cidx = (long long)m * ldc + n;
            if (accum) Cb[cidx] += v;
            else       Cb[cidx]  = v;
        }
    }
}

// ---------------- row softmax (in place), one block per row ----------------
__global__ __launch_bounds__(256)
void softmax_kernel(float* __restrict__ data, int n)
{
    float* p = data + (long long)blockIdx.x * n;
    __shared__ float red[256];
    const int tid = threadIdx.x;

    float m = -1e30f;
    for (int i = tid; i < n; i += 256) m = fmaxf(m, p[i]);
    red[tid] = m;
    __syncthreads();
    for (int s = 128; s > 0; s >>= 1) {
        if (tid < s) red[tid] = fmaxf(red[tid], red[tid + s]);
        __syncthreads();
    }
    m = red[0];
    __syncthreads();

    float sum = 0.0f;
    for (int i = tid; i < n; i += 256) {
        float e = __expf(p[i] - m);
        p[i] = e;
        sum += e;
    }
    red[tid] = sum;
    __syncthreads();
    for (int s = 128; s > 0; s >>= 1) {
        if (tid < s) red[tid] += red[tid + s];
        __syncthreads();
    }
    float inv = 1.0f / red[0];
    for (int i = tid; i < n; i += 256) p[i] *= inv;
}

// ---------------- elementwise ----------------
__global__ void mean2_kernel(const float* __restrict__ a, const float* __restrict__ b,
                             float* __restrict__ o, int n)
{
    int i = blockIdx.x * blockDim.x + threadIdx.x;
    if (i < n) o[i] = 0.5f * (a[i] + b[i]);
}

__global__ void final_gate_kernel(const float* __restrict__ o, const float* __restrict__ rec,
                                  const float* __restrict__ gpre, float* __restrict__ outp, int n)
{
    int i = blockIdx.x * blockDim.x + threadIdx.x;
    if (i < n) {
        float s = 1.0f / (1.0f + __expf(-gpre[i]));
        outp[i] = o[i] * (1.0f - s) + rec[i] * s;
    }
}

// ---------------- host launch ----------------
static inline dim3 ggrid(int M, int N, int Z) { return dim3(N / BN, M / BM, Z); }

extern "C" void kernel_launch(void* const* d_in, const int* in_sizes, int n_in,
                              void* d_out, int out_size)
{
    const float* hs   = (const float*)d_in[0];
    const float* past = (const float*)d_in[1];
    const float* Wq = (const float*)d_in[2],  *bq = (const float*)d_in[3];
    const float* Wk = (const float*)d_in[4],  *bk = (const float*)d_in[5];
    const float* Wv = (const float*)d_in[6],  *bv = (const float*)d_in[7];
    const float* Wo = (const float*)d_in[8],  *bo = (const float*)d_in[9];
    const float* Wrq = (const float*)d_in[10], *brq = (const float*)d_in[11];
    const float* Wrk = (const float*)d_in[12], *brk = (const float*)d_in[13];
    const float* Wrv = (const float*)d_in[14], *brv = (const float*)d_in[15];
    const float* Wg = (const float*)d_in[16],  *bg = (const float*)d_in[17];
    float* outp = (float*)d_out;

    float *q, *k, *v, *ctx, *out, *rq, *rk, *rv, *rctx0, *rctx1, *rec, *gate, *scores;
    cudaGetSymbolAddress((void**)&q,      g_q);
    cudaGetSymbolAddress((void**)&k,      g_k);
    cudaGetSymbolAddress((void**)&v,      g_v);
    cudaGetSymbolAddress((void**)&ctx,    g_ctx);
    cudaGetSymbolAddress((void**)&out,    g_out);
    cudaGetSymbolAddress((void**)&rq,     g_rq);
    cudaGetSymbolAddress((void**)&rk,     g_rk);
    cudaGetSymbolAddress((void**)&rv,     g_rv);
    cudaGetSymbolAddress((void**)&rctx0,  g_rctx0);
    cudaGetSymbolAddress((void**)&rctx1,  g_rctx1);
    cudaGetSymbolAddress((void**)&rec,    g_rec);
    cudaGetSymbolAddress((void**)&gate,   g_gate);
    cudaGetSymbolAddress((void**)&scores, g_scores);

    const dim3 blk(256);
    const long long SS = (long long)SEQ * SEQ;
    const int nElem = SEQ * HID;
    const dim3 egrid((nElem + 255) / 256);

    // ---- Q/K/V projections ----
    gemm_kernel<false><<<ggrid(SEQ, HID, 1), blk>>>(hs, HID, 0, Wq, HID, 0, bq, q, HID, 0, SEQ, HID, HID, 1.0f, 0);
    gemm_kernel<false><<<ggrid(SEQ, HID, 1), blk>>>(hs, HID, 0, Wk, HID, 0, bk, k, HID, 0, SEQ, HID, HID, 1.0f, 0);
    gemm_kernel<false><<<ggrid(SEQ, HID, 1), blk>>>(hs, HID, 0, Wv, HID, 0, bv, v, HID, 0, SEQ, HID, HID, 1.0f, 0);

    // ---- self attention: scores = scale * Q Kᵀ (per head), softmax, ctx = A V ----
    gemm_kernel<true ><<<ggrid(SEQ, SEQ, NHEAD), blk>>>(q, HID, DHEAD, k, HID, DHEAD, nullptr,
                                                        scores, SEQ, SS, SEQ, SEQ, DHEAD, ATT_SCALE, 0);
    softmax_kernel<<<NHEAD * SEQ, blk>>>(scores, SEQ);
    gemm_kernel<false><<<ggrid(SEQ, DHEAD, NHEAD), blk>>>(scores, SEQ, SS, v, HID, DHEAD, nullptr,
                                                          ctx, HID, DHEAD, SEQ, DHEAD, SEQ, 1.0f, 0);
    gemm_kernel<false><<<ggrid(SEQ, HID, 1), blk>>>(ctx, HID, 0, Wo, HID, 0, bo, out, HID, 0, SEQ, HID, HID, 1.0f, 0);

    // ---- recursive attention over P=2 past states ----
    gemm_kernel<false><<<ggrid(SEQ, HID, 1), blk>>>(out, HID, 0, Wrq, HID, 0, brq, rq, HID, 0, SEQ, HID, HID, 1.0f, 0);

    float* rctx_dst[2] = {rctx0, rctx1};
    for (int p = 0; p < 2; p++) {
        const float* pastp = past + (long long)p * SEQ * HID;
        gemm_kernel<false><<<ggrid(SEQ, HID, 1), blk>>>(pastp, HID, 0, Wrk, HID, 0, brk, rk, HID, 0, SEQ, HID, HID, 1.0f, 0);
        gemm_kernel<false><<<ggrid(SEQ, HID, 1), blk>>>(pastp, HID, 0, Wrv, HID, 0, brv, rv, HID, 0, SEQ, HID, HID, 1.0f, 0);
        gemm_kernel<true ><<<ggrid(SEQ, SEQ, NHEAD), blk>>>(rq, HID, DHEAD, rk, HID, DHEAD, nullptr,
                                                            scores, SEQ, SS, SEQ, SEQ, DHEAD, ATT_SCALE, 0);
        softmax_kernel<<<NHEAD * SEQ, blk>>>(scores, SEQ);
        gemm_kernel<false><<<ggrid(SEQ, DHEAD, NHEAD), blk>>>(scores, SEQ, SS, rv, HID, DHEAD, nullptr,
                                                              rctx_dst[p], HID, DHEAD, SEQ, DHEAD, SEQ, 1.0f, 0);
    }
    mean2_kernel<<<egrid, blk>>>(rctx0, rctx1, rec, nElem);

    // ---- gate = sigmoid([out, rec] @ Wg + bg); blend ----
    gemm_kernel<false><<<ggrid(SEQ, HID, 1), blk>>>(out, HID, 0, Wg, HID, 0, bg, gate, HID, 0, SEQ, HID, HID, 1.0f, 0);
    gemm_kernel<false><<<ggrid(SEQ, HID, 1), blk>>>(rec, HID, 0, Wg + (long long)HID * HID, HID, 0, nullptr,
                                                    gate, HID, 0, SEQ, HID, HID, 1.0f, 1);
    final_gate_kernel<<<egrid, blk>>>(out, rec, gate, outp, nElem);
}

// round 4
// speedup vs baseline: 2.3553x; 2.3553x over previous
#include <cuda_runtime.h>
#include <math.h>
#include <stdint.h>

// Problem constants
#define SEQ   2048
#define HID   1024
#define NHEAD 16
#define DHEAD 64
#define ATT_SCALE 0.125f   // 1/sqrt(64)

// ---------------- scratch (__device__ globals; no allocations allowed) ----------------
__device__ __align__(16) float g_q[SEQ * HID];
__device__ __align__(16) float g_k[SEQ * HID];
__device__ __align__(16) float g_v[SEQ * HID];
__device__ __align__(16) float g_ctx[SEQ * HID];
__device__ __align__(16) float g_out[SEQ * HID];
__device__ __align__(16) float g_rq[SEQ * HID];
__device__ __align__(16) float g_rk[SEQ * HID];
__device__ __align__(16) float g_rv[SEQ * HID];
__device__ __align__(16) float g_rctx0[SEQ * HID];
__device__ __align__(16) float g_rctx1[SEQ * HID];
__device__ __align__(16) float g_rec[SEQ * HID];
__device__ __align__(16) float g_gate[SEQ * HID];
__device__ __align__(16) float g_scores[(size_t)NHEAD * SEQ * SEQ];   // 256 MB
__device__ __align__(16) float2 g_stats[NHEAD * SEQ];                 // row max, 1/sum

// ---------------- tf32 helpers ----------------
__device__ __forceinline__ float to_tf32(float x) {
    uint32_t u;
    asm("cvt.rna.tf32.f32 %0, %1;" : "=r"(u) : "f"(x));
    return __uint_as_float(u);
}

__device__ __forceinline__ void mma_tf32(float* c, const uint32_t* a, const uint32_t* b) {
    asm volatile(
        "mma.sync.aligned.m16n8k8.row.col.f32.tf32.tf32.f32 "
        "{%0,%1,%2,%3}, {%4,%5,%6,%7}, {%8,%9}, {%0,%1,%2,%3};"
        : "+f"(c[0]), "+f"(c[1]), "+f"(c[2]), "+f"(c[3])
        : "r"(a[0]), "r"(a[1]), "r"(a[2]), "r"(a[3]), "r"(b[0]), "r"(b[1]));
}

// ---------------- tf32 tensor-core GEMM ----------------
// C[m][n] = alpha * sum_k A[m][k] * (TB ? B[n][k] : B[k][n]) (+bias[n]) (+=C if accum)
// SM: apply x -> exp(x - stats.m)*stats.invl to A elements (fused softmax for AV).
// 256 threads = 8 warps, warp tile WM x WN of m16n8k8 fragments.
template <int BM, int BN, int BK, int WM, int WN, bool TB, bool SM>
__global__ __launch_bounds__(256, 1)
void mma_gemm(const float* __restrict__ A, int lda, long long sA,
              const float* __restrict__ B, int ldb, long long sB,
              const float* __restrict__ bias,
              const float2* __restrict__ stats, long long sStats,
              float* __restrict__ C, int ldc, long long sC,
              int K, float alpha, int accum)
{
    constexpr int WARPS_M = BM / WM;
    constexpr int WARPS_N = BN / WN;
    static_assert(WARPS_M * WARPS_N == 8, "need 8 warps");
    constexpr int MF = WM / 16;
    constexpr int NF = WN / 8;

    // A: m-major, stride BK+4 words -> fragment LDS banks (4g+tg) all distinct.
    __shared__ float As[BM][BK + 4];
    // B: NT -> n-major stride BK+4 (banks 4g+tg); NN -> k-major stride BN+8 (banks 8tg+g).
    constexpr int BSR = TB ? BN : BK;
    constexpr int BSC = TB ? (BK + 4) : (BN + 8);
    __shared__ float Bs[BSR][BSC];

    const int tid  = threadIdx.x;
    const int wid  = tid >> 5;
    const int lane = tid & 31;
    const int g    = lane >> 2;   // groupID 0..7
    const int tg   = lane & 3;    // threadInGroup 0..3
    const int wm   = (wid % WARPS_M) * WM;
    const int wn   = (wid / WARPS_M) * WN;
    const int row0 = blockIdx.y * BM;
    const int col0 = blockIdx.x * BN;

    const float* Ab = A + blockIdx.z * sA;
    const float* Bb = B + blockIdx.z * sB;
    float* Cb = C + blockIdx.z * sC;
    const float2* stb = SM ? (stats + blockIdx.z * sStats) : nullptr;

    float acc[MF][NF][4];
#pragma unroll
    for (int i = 0; i < MF; i++)
#pragma unroll
        for (int j = 0; j < NF; j++)
#pragma unroll
            for (int r = 0; r < 4; r++) acc[i][j][r] = 0.0f;

    for (int k0 = 0; k0 < K; k0 += BK) {
        // ---- load A tile (BM x BK), float4 along k, tf32-convert, optional softmax ----
#pragma unroll
        for (int i = 0; i < BM * BK / 1024; i++) {
            int idx = (tid + i * 256) * 4;
            int m = idx / BK, kk = idx % BK;
            float4 v = *(const float4*)(Ab + (long long)(row0 + m) * lda + k0 + kk);
            if (SM) {
                float2 s = stb[row0 + m];
                v.x = __expf(v.x - s.x) * s.y;
                v.y = __expf(v.y - s.x) * s.y;
                v.z = __expf(v.z - s.x) * s.y;
                v.w = __expf(v.w - s.x) * s.y;
            }
            v.x = to_tf32(v.x); v.y = to_tf32(v.y);
            v.z = to_tf32(v.z); v.w = to_tf32(v.w);
            *(float4*)&As[m][kk] = v;
        }
        // ---- load B tile ----
#pragma unroll
        for (int i = 0; i < BN * BK / 1024; i++) {
            int idx = (tid + i * 256) * 4;
            if (TB) {
                int n = idx / BK, kk = idx % BK;
                float4 v = *(const float4*)(Bb + (long long)(col0 + n) * ldb + k0 + kk);
                v.x = to_tf32(v.x); v.y = to_tf32(v.y);
                v.z = to_tf32(v.z); v.w = to_tf32(v.w);
                *(float4*)&Bs[n][kk] = v;
            } else {
                int kk = idx / BN, n = idx % BN;
                float4 v = *(const float4*)(Bb + (long long)(k0 + kk) * ldb + col0 + n);
                v.x = to_tf32(v.x); v.y = to_tf32(v.y);
                v.z = to_tf32(v.z); v.w = to_tf32(v.w);
                *(float4*)&Bs[kk][n] = v;
            }
        }
        __syncthreads();

#pragma unroll
        for (int ks = 0; ks < BK; ks += 8) {
            uint32_t af[MF][4], bf[NF][2];
#pragma unroll
            for (int i = 0; i < MF; i++) {
                int m = wm + i * 16 + g;
                af[i][0] = __float_as_uint(As[m][ks + tg]);
                af[i][1] = __float_as_uint(As[m + 8][ks + tg]);
                af[i][2] = __float_as_uint(As[m][ks + tg + 4]);
                af[i][3] = __float_as_uint(As[m + 8][ks + tg + 4]);
            }
#pragma unroll
            for (int j = 0; j < NF; j++) {
                int n = wn + j * 8 + g;
                if (TB) {
                    bf[j][0] = __float_as_uint(Bs[n][ks + tg]);
                    bf[j][1] = __float_as_uint(Bs[n][ks + tg + 4]);
                } else {
                    bf[j][0] = __float_as_uint(Bs[ks + tg][n]);
                    bf[j][1] = __float_as_uint(Bs[ks + tg + 4][n]);
                }
            }
#pragma unroll
            for (int i = 0; i < MF; i++)
#pragma unroll
                for (int j = 0; j < NF; j++)
                    mma_tf32(acc[i][j], af[i], bf[j]);
        }
        __syncthreads();
    }

    // ---- epilogue: c0,c1 at (g, 2tg..2tg+1), c2,c3 at (g+8, ...) ----
#pragma unroll
    for (int i = 0; i < MF; i++) {
#pragma unroll
        for (int j = 0; j < NF; j++) {
            int m0 = row0 + wm + i * 16 + g;
            int n0 = col0 + wn + j * 8 + 2 * tg;
            float2 r0 = make_float2(acc[i][j][0] * alpha, acc[i][j][1] * alpha);
            float2 r1 = make_float2(acc[i][j][2] * alpha, acc[i][j][3] * alpha);
            if (bias) {
                float bx = bias[n0], by = bias[n0 + 1];
                r0.x += bx; r0.y += by; r1.x += bx; r1.y += by;
            }
            float2* p0 = (float2*)&Cb[(long long)m0 * ldc + n0];
            float2* p1 = (float2*)&Cb[(long long)(m0 + 8) * ldc + n0];
            if (accum) {
                float2 o0 = *p0, o1 = *p1;
                r0.x += o0.x; r0.y += o0.y; r1.x += o1.x; r1.y += o1.y;
            }
            *p0 = r0;
            *p1 = r1;
        }
    }
}

// ---------------- row stats for fused softmax: per row compute (max, 1/sum(exp)) ----------------
__global__ __launch_bounds__(256)
void row_stats_kernel(const float* __restrict__ sc, float2* __restrict__ st)
{
    const float* p = sc + (long long)blockIdx.x * SEQ;
    const int tid = threadIdx.x;
    __shared__ float red[256];

    float4 v0 = *(const float4*)(p + tid * 4);
    float4 v1 = *(const float4*)(p + SEQ / 2 + tid * 4);

    float m = fmaxf(fmaxf(fmaxf(v0.x, v0.y), fmaxf(v0.z, v0.w)),
                    fmaxf(fmaxf(v1.x, v1.y), fmaxf(v1.z, v1.w)));
    red[tid] = m;
    __syncthreads();
    for (int s = 128; s > 0; s >>= 1) {
        if (tid < s) red[tid] = fmaxf(red[tid], red[tid + s]);
        __syncthreads();
    }
    m = red[0];
    __syncthreads();

    float sum = __expf(v0.x - m) + __expf(v0.y - m) + __expf(v0.z - m) + __expf(v0.w - m)
              + __expf(v1.x - m) + __expf(v1.y - m) + __expf(v1.z - m) + __expf(v1.w - m);
    red[tid] = sum;
    __syncthreads();
    for (int s = 128; s > 0; s >>= 1) {
        if (tid < s) red[tid] += red[tid + s];
        __syncthreads();
    }
    if (tid == 0) st[blockIdx.x] = make_float2(m, 1.0f / red[0]);
}

// ---------------- elementwise ----------------
__global__ void mean2_kernel(const float* __restrict__ a, const float* __restrict__ b,
                             float* __restrict__ o, int n)
{
    int i = blockIdx.x * blockDim.x + threadIdx.x;
    if (i < n) o[i] = 0.5f * (a[i] + b[i]);
}

__global__ void final_gate_kernel(const float* __restrict__ o, const float* __restrict__ rec,
                                  const float* __restrict__ gpre, float* __restrict__ outp, int n)
{
    int i = blockIdx.x * blockDim.x + threadIdx.x;
    if (i < n) {
        float s = 1.0f / (1.0f + __expf(-gpre[i]));
        outp[i] = o[i] * (1.0f - s) + rec[i] * s;
    }
}

// ---------------- host launch ----------------
extern "C" void kernel_launch(void* const* d_in, const int* in_sizes, int n_in,
                              void* d_out, int out_size)
{
    const float* hs   = (const float*)d_in[0];
    const float* past = (const float*)d_in[1];
    const float* Wq = (const float*)d_in[2],  *bq = (const float*)d_in[3];
    const float* Wk = (const float*)d_in[4],  *bk = (const float*)d_in[5];
    const float* Wv = (const float*)d_in[6],  *bv = (const float*)d_in[7];
    const float* Wo = (const float*)d_in[8],  *bo = (const float*)d_in[9];
    const float* Wrq = (const float*)d_in[10], *brq = (const float*)d_in[11];
    const float* Wrk = (const float*)d_in[12], *brk = (const float*)d_in[13];
    const float* Wrv = (const float*)d_in[14], *brv = (const float*)d_in[15];
    const float* Wg = (const float*)d_in[16],  *bg = (const float*)d_in[17];
    float* outp = (float*)d_out;

    float *q, *k, *v, *ctx, *out, *rq, *rk, *rv, *rctx0, *rctx1, *rec, *gate, *scores;
    float2* stats;
    cudaGetSymbolAddress((void**)&q,      g_q);
    cudaGetSymbolAddress((void**)&k,      g_k);
    cudaGetSymbolAddress((void**)&v,      g_v);
    cudaGetSymbolAddress((void**)&ctx,    g_ctx);
    cudaGetSymbolAddress((void**)&out,    g_out);
    cudaGetSymbolAddress((void**)&rq,     g_rq);
    cudaGetSymbolAddress((void**)&rk,     g_rk);
    cudaGetSymbolAddress((void**)&rv,     g_rv);
    cudaGetSymbolAddress((void**)&rctx0,  g_rctx0);
    cudaGetSymbolAddress((void**)&rctx1,  g_rctx1);
    cudaGetSymbolAddress((void**)&rec,    g_rec);
    cudaGetSymbolAddress((void**)&gate,   g_gate);
    cudaGetSymbolAddress((void**)&scores, g_scores);
    cudaGetSymbolAddress((void**)&stats,  g_stats);

    const dim3 blk(256);
    const long long SS = (long long)SEQ * SEQ;
    const int nElem = SEQ * HID;
    const dim3 egrid((nElem + 255) / 256);

    // Grids
    const dim3 gDense(HID / 128, SEQ / 128, 1);     // 8 x 16 = 128 blocks
    const dim3 gQK(SEQ / 128, SEQ / 128, NHEAD);    // 16 x 16 x 16
    const dim3 gAV(DHEAD / 64, SEQ / 128, NHEAD);   // 1 x 16 x 16

    // dense: <BM=128,BN=128,BK=32,WM=32,WN=64, NN, no-softmax>
    #define DENSE mma_gemm<128,128,32,32,64,false,false>
    // qk^T:  <..., NT>
    #define QKT   mma_gemm<128,128,32,32,64,true ,false>
    // AV:    <BM=128,BN=64, NN, fused softmax on A>
    #define AV    mma_gemm<128, 64,32,32,32,false,true >

    // ---- Q/K/V projections ----
    DENSE<<<gDense, blk>>>(hs, HID, 0, Wq, HID, 0, bq, nullptr, 0, q, HID, 0, HID, 1.0f, 0);
    DENSE<<<gDense, blk>>>(hs, HID, 0, Wk, HID, 0, bk, nullptr, 0, k, HID, 0, HID, 1.0f, 0);
    DENSE<<<gDense, blk>>>(hs, HID, 0, Wv, HID, 0, bv, nullptr, 0, v, HID, 0, HID, 1.0f, 0);

    // ---- self attention ----
    QKT<<<gQK, blk>>>(q, HID, DHEAD, k, HID, DHEAD, nullptr, nullptr, 0,
                      scores, SEQ, SS, DHEAD, ATT_SCALE, 0);
    row_stats_kernel<<<NHEAD * SEQ, blk>>>(scores, stats);
    AV<<<gAV, blk>>>(scores, SEQ, SS, v, HID, DHEAD, nullptr, stats, SEQ,
                     ctx, HID, DHEAD, SEQ, 1.0f, 0);
    DENSE<<<gDense, blk>>>(ctx, HID, 0, Wo, HID, 0, bo, nullptr, 0, out, HID, 0, HID, 1.0f, 0);

    // ---- recursive attention over P=2 past states ----
    DENSE<<<gDense, blk>>>(out, HID, 0, Wrq, HID, 0, brq, nullptr, 0, rq, HID, 0, HID, 1.0f, 0);

    float* rctx_dst[2] = {rctx0, rctx1};
    for (int p = 0; p < 2; p++) {
        const float* pastp = past + (long long)p * SEQ * HID;
        DENSE<<<gDense, blk>>>(pastp, HID, 0, Wrk, HID, 0, brk, nullptr, 0, rk, HID, 0, HID, 1.0f, 0);
        DENSE<<<gDense, blk>>>(pastp, HID, 0, Wrv, HID, 0, brv, nullptr, 0, rv, HID, 0, HID, 1.0f, 0);
        QKT<<<gQK, blk>>>(rq, HID, DHEAD, rk, HID, DHEAD, nullptr, nullptr, 0,
                          scores, SEQ, SS, DHEAD, ATT_SCALE, 0);
        row_stats_kernel<<<NHEAD * SEQ, blk>>>(scores, stats);
        AV<<<gAV, blk>>>(scores, SEQ, SS, rv, HID, DHEAD, nullptr, stats, SEQ,
                         rctx_dst[p], HID, DHEAD, SEQ, 1.0f, 0);
    }
    mean2_kernel<<<egrid, blk>>>(rctx0, rctx1, rec, nElem);

    // ---- gate = sigmoid([out, rec] @ Wg + bg); blend ----
    DENSE<<<gDense, blk>>>(out, HID, 0, Wg, HID, 0, bg, nullptr, 0, gate, HID, 0, HID, 1.0f, 0);
    DENSE<<<gDense, blk>>>(rec, HID, 0, Wg + (long long)HID * HID, HID, 0, nullptr, nullptr, 0,
                           gate, HID, 0, HID, 1.0f, 1);
    final_gate_kernel<<<egrid, blk>>>(out, rec, gate, outp, nElem);
}

// round 5
// speedup vs baseline: 3.3258x; 1.4121x over previous
#include <cuda_runtime.h>
#include <math.h>
#include <stdint.h>

// Problem constants
#define SEQ   2048
#define HID   1024
#define NHEAD 16
#define DHEAD 64
#define ATT_SCALE 0.125f                       // 1/sqrt(64)
#define CEXP (0.125f * 1.44269504088896f)      // scale * log2(e)

// ---------------- scratch (__device__ globals; no allocations allowed) ----------------
__device__ __align__(16) float g_q[SEQ * HID];
__device__ __align__(16) float g_k[SEQ * HID];
__device__ __align__(16) float g_v[SEQ * HID];
__device__ __align__(16) float g_ctx[SEQ * HID];
__device__ __align__(16) float g_out[SEQ * HID];
__device__ __align__(16) float g_rq[SEQ * HID];
__device__ __align__(16) float g_rk[SEQ * HID];
__device__ __align__(16) float g_rv[SEQ * HID];
__device__ __align__(16) float g_rctx0[SEQ * HID];
__device__ __align__(16) float g_rctx1[SEQ * HID];
__device__ __align__(16) float g_rec[SEQ * HID];
__device__ __align__(16) float g_gate[SEQ * HID];

// ---------------- tf32 helpers ----------------
__device__ __forceinline__ float to_tf32(float x) {
    uint32_t u;
    asm("cvt.rna.tf32.f32 %0, %1;" : "=r"(u) : "f"(x));
    return __uint_as_float(u);
}

__device__ __forceinline__ void mma_tf32(float* c, const uint32_t* a, const uint32_t* b) {
    asm volatile(
        "mma.sync.aligned.m16n8k8.row.col.f32.tf32.tf32.f32 "
        "{%0,%1,%2,%3}, {%4,%5,%6,%7}, {%8,%9}, {%0,%1,%2,%3};"
        : "+f"(c[0]), "+f"(c[1]), "+f"(c[2]), "+f"(c[3])
        : "r"(a[0]), "r"(a[1]), "r"(a[2]), "r"(a[3]), "r"(b[0]), "r"(b[1]));
}

// ============================================================================
// Fused flash attention: O = softmax(scale * Q K^T) V   per head.
// Grid: (SEQ/128, NHEAD). Block: 256 threads = 8 warps, warp tile 16q x 128k.
// Q,K,V,O all [SEQ][HID] with head h at columns h*64 .. h*64+63.
// ============================================================================
#define FLASH_SMEM 174080

__global__ __launch_bounds__(256, 1)
void flash_kernel(const float* __restrict__ Qg, const float* __restrict__ Kg,
                  const float* __restrict__ Vg, float* __restrict__ Og)
{
    extern __shared__ char smem[];
    float* Qs = (float*)smem;                      // [128][68]
    float* Ks = (float*)(smem + 34816);            // [128][68]
    float* Vs = (float*)(smem + 69632);            // [128][72]
    float* Ps = (float*)(smem + 106496);           // [8 warps][16][132]

    const int tid  = threadIdx.x;
    const int wid  = tid >> 5;
    const int lane = tid & 31;
    const int g    = lane >> 2;     // 0..7
    const int tg   = lane & 3;      // 0..3
    const int q0   = blockIdx.x * 128;
    const int hcol = blockIdx.y * DHEAD;
    float* Pw = Ps + wid * (16 * 132);

    // ---- load Q tile [128][64] -> Qs (tf32), once ----
#pragma unroll
    for (int i = 0; i < 8; i++) {
        int lin = tid + i * 256;
        int row = lin >> 4, c = (lin & 15) * 4;
        float4 v = *(const float4*)&Qg[(long long)(q0 + row) * HID + hcol + c];
        v.x = to_tf32(v.x); v.y = to_tf32(v.y);
        v.z = to_tf32(v.z); v.w = to_tf32(v.w);
        *(float4*)&Qs[row * 68 + c] = v;
    }

    float m_lo = -1e30f, m_hi = -1e30f;
    float l_lo = 0.0f,   l_hi = 0.0f;
    float out[8][4];
#pragma unroll
    for (int j = 0; j < 8; j++)
#pragma unroll
        for (int r = 0; r < 4; r++) out[j][r] = 0.0f;

    const int mrow = wid * 16 + g;   // warp's low q-row within tile

    for (int t = 0; t < SEQ / 128; t++) {
        __syncthreads();   // previous iter's Ks/Vs reads (and Q store on t=0) done
        // ---- load K,V tiles [128][64] ----
        const int kv0 = t * 128;
#pragma unroll
        for (int i = 0; i < 8; i++) {
            int lin = tid + i * 256;
            int row = lin >> 4, c = (lin & 15) * 4;
            float4 v = *(const float4*)&Kg[(long long)(kv0 + row) * HID + hcol + c];
            v.x = to_tf32(v.x); v.y = to_tf32(v.y);
            v.z = to_tf32(v.z); v.w = to_tf32(v.w);
            *(float4*)&Ks[row * 68 + c] = v;
        }
#pragma unroll
        for (int i = 0; i < 8; i++) {
            int lin = tid + i * 256;
            int row = lin >> 4, c = (lin & 15) * 4;
            float4 v = *(const float4*)&Vg[(long long)(kv0 + row) * HID + hcol + c];
            v.x = to_tf32(v.x); v.y = to_tf32(v.y);
            v.z = to_tf32(v.z); v.w = to_tf32(v.w);
            *(float4*)&Vs[row * 72 + c] = v;
        }
        __syncthreads();

        // ---- S = Q K^T (warp: 16 x 128, raw scores) ----
        float s[16][4];
#pragma unroll
        for (int j = 0; j < 16; j++)
#pragma unroll
            for (int r = 0; r < 4; r++) s[j][r] = 0.0f;

#pragma unroll
        for (int ks = 0; ks < DHEAD; ks += 8) {
            uint32_t aq[4];
            aq[0] = __float_as_uint(Qs[mrow * 68 + ks + tg]);
            aq[1] = __float_as_uint(Qs[(mrow + 8) * 68 + ks + tg]);
            aq[2] = __float_as_uint(Qs[mrow * 68 + ks + tg + 4]);
            aq[3] = __float_as_uint(Qs[(mrow + 8) * 68 + ks + tg + 4]);
#pragma unroll
            for (int j = 0; j < 16; j++) {
                uint32_t bf[2];
                int nr = j * 8 + g;
                bf[0] = __float_as_uint(Ks[nr * 68 + ks + tg]);
                bf[1] = __float_as_uint(Ks[nr * 68 + ks + tg + 4]);
                mma_tf32(s[j], aq, bf);
            }
        }

        // ---- online softmax (rows g and g+8 of the warp tile) ----
        float vm0 = -1e30f, vm1 = -1e30f;
#pragma unroll
        for (int j = 0; j < 16; j++) {
            vm0 = fmaxf(vm0, fmaxf(s[j][0], s[j][1]));
            vm1 = fmaxf(vm1, fmaxf(s[j][2], s[j][3]));
        }
        vm0 = fmaxf(vm0, __shfl_xor_sync(0xffffffffu, vm0, 1));
        vm0 = fmaxf(vm0, __shfl_xor_sync(0xffffffffu, vm0, 2));
        vm1 = fmaxf(vm1, __shfl_xor_sync(0xffffffffu, vm1, 1));
        vm1 = fmaxf(vm1, __shfl_xor_sync(0xffffffffu, vm1, 2));

        float mn0 = fmaxf(m_lo, vm0), mn1 = fmaxf(m_hi, vm1);
        float corr0 = exp2f((m_lo - mn0) * CEXP);
        float corr1 = exp2f((m_hi - mn1) * CEXP);
        m_lo = mn0; m_hi = mn1;

        float sl0 = 0.0f, sl1 = 0.0f;
#pragma unroll
        for (int j = 0; j < 16; j++) {
            float p0 = exp2f((s[j][0] - mn0) * CEXP);
            float p1 = exp2f((s[j][1] - mn0) * CEXP);
            float p2 = exp2f((s[j][2] - mn1) * CEXP);
            float p3 = exp2f((s[j][3] - mn1) * CEXP);
            sl0 += p0 + p1;
            sl1 += p2 + p3;
            float2 lo = make_float2(to_tf32(p0), to_tf32(p1));
            float2 hi = make_float2(to_tf32(p2), to_tf32(p3));
            *(float2*)&Pw[g * 132 + j * 8 + 2 * tg] = lo;
            *(float2*)&Pw[(g + 8) * 132 + j * 8 + 2 * tg] = hi;
        }
        sl0 += __shfl_xor_sync(0xffffffffu, sl0, 1);
        sl0 += __shfl_xor_sync(0xffffffffu, sl0, 2);
        sl1 += __shfl_xor_sync(0xffffffffu, sl1, 1);
        sl1 += __shfl_xor_sync(0xffffffffu, sl1, 2);
        l_lo = l_lo * corr0 + sl0;
        l_hi = l_hi * corr1 + sl1;

#pragma unroll
        for (int j = 0; j < 8; j++) {
            out[j][0] *= corr0; out[j][1] *= corr0;
            out[j][2] *= corr1; out[j][3] *= corr1;
        }

        __syncwarp();   // P visible across the warp

        // ---- out += P V (warp: 16 x 64, K-dim = 128 keys) ----
#pragma unroll
        for (int ks = 0; ks < 128; ks += 8) {
            uint32_t ap[4];
            ap[0] = __float_as_uint(Pw[g * 132 + ks + tg]);
            ap[1] = __float_as_uint(Pw[(g + 8) * 132 + ks + tg]);
            ap[2] = __float_as_uint(Pw[g * 132 + ks + tg + 4]);
            ap[3] = __float_as_uint(Pw[(g + 8) * 132 + ks + tg + 4]);
#pragma unroll
            for (int j = 0; j < 8; j++) {
                uint32_t bf[2];
                bf[0] = __float_as_uint(Vs[(ks + tg) * 72 + j * 8 + g]);
                bf[1] = __float_as_uint(Vs[(ks + tg + 4) * 72 + j * 8 + g]);
                mma_tf32(out[j], ap, bf);
            }
        }
        // next iter's leading __syncthreads orders P reads vs next P writes
    }

    // ---- epilogue: normalize and store ----
    float il0 = 1.0f / l_lo, il1 = 1.0f / l_hi;
    const int gr = q0 + mrow;
#pragma unroll
    for (int j = 0; j < 8; j++) {
        int n0 = hcol + j * 8 + 2 * tg;
        float2 r0 = make_float2(out[j][0] * il0, out[j][1] * il0);
        float2 r1 = make_float2(out[j][2] * il1, out[j][3] * il1);
        *(float2*)&Og[(long long)gr * HID + n0]       = r0;
        *(float2*)&Og[(long long)(gr + 8) * HID + n0] = r1;
    }
}

// ---------------- tf32 tensor-core GEMM (dense projections) ----------------
// C[m][n] = alpha * sum_k A[m][k] * B[k][n] (+bias[n]) (+=C if accum)
template <int BM, int BN, int BK, int WM, int WN>
__global__ __launch_bounds__(256, 1)
void mma_gemm(const float* __restrict__ A, int lda,
              const float* __restrict__ B, int ldb,
              const float* __restrict__ bias,
              float* __restrict__ C, int ldc,
              int K, float alpha, int accum)
{
    constexpr int WARPS_M = BM / WM;
    constexpr int MF = WM / 16;
    constexpr int NF = WN / 8;

    __shared__ float As[BM][BK + 4];
    __shared__ float Bs[BK][BN + 8];

    const int tid  = threadIdx.x;
    const int wid  = tid >> 5;
    const int lane = tid & 31;
    const int g    = lane >> 2;
    const int tg   = lane & 3;
    const int wm   = (wid % WARPS_M) * WM;
    const int wn   = (wid / WARPS_M) * WN;
    const int row0 = blockIdx.y * BM;
    const int col0 = blockIdx.x * BN;

    float acc[MF][NF][4];
#pragma unroll
    for (int i = 0; i < MF; i++)
#pragma unroll
        for (int j = 0; j < NF; j++)
#pragma unroll
            for (int r = 0; r < 4; r++) acc[i][j][r] = 0.0f;

    for (int k0 = 0; k0 < K; k0 += BK) {
#pragma unroll
        for (int i = 0; i < BM * BK / 1024; i++) {
            int idx = (tid + i * 256) * 4;
            int m = idx / BK, kk = idx % BK;
            float4 v = *(const float4*)(A + (long long)(row0 + m) * lda + k0 + kk);
            v.x = to_tf32(v.x); v.y = to_tf32(v.y);
            v.z = to_tf32(v.z); v.w = to_tf32(v.w);
            *(float4*)&As[m][kk] = v;
        }
#pragma unroll
        for (int i = 0; i < BN * BK / 1024; i++) {
            int idx = (tid + i * 256) * 4;
            int kk = idx / BN, n = idx % BN;
            float4 v = *(const float4*)(B + (long long)(k0 + kk) * ldb + col0 + n);
            v.x = to_tf32(v.x); v.y = to_tf32(v.y);
            v.z = to_tf32(v.z); v.w = to_tf32(v.w);
            *(float4*)&Bs[kk][n] = v;
        }
        __syncthreads();

#pragma unroll
        for (int ks = 0; ks < BK; ks += 8) {
            uint32_t af[MF][4], bf[NF][2];
#pragma unroll
            for (int i = 0; i < MF; i++) {
                int m = wm + i * 16 + g;
                af[i][0] = __float_as_uint(As[m][ks + tg]);
                af[i][1] = __float_as_uint(As[m + 8][ks + tg]);
                af[i][2] = __float_as_uint(As[m][ks + tg + 4]);
                af[i][3] = __float_as_uint(As[m + 8][ks + tg + 4]);
            }
#pragma unroll
            for (int j = 0; j < NF; j++) {
                int n = wn + j * 8 + g;
                bf[j][0] = __float_as_uint(Bs[ks + tg][n]);
                bf[j][1] = __float_as_uint(Bs[ks + tg + 4][n]);
            }
#pragma unroll
            for (int i = 0; i < MF; i++)
#pragma unroll
                for (int j = 0; j < NF; j++)
                    mma_tf32(acc[i][j], af[i], bf[j]);
        }
        __syncthreads();
    }

#pragma unroll
    for (int i = 0; i < MF; i++) {
#pragma unroll
        for (int j = 0; j < NF; j++) {
            int m0 = row0 + wm + i * 16 + g;
            int n0 = col0 + wn + j * 8 + 2 * tg;
            float2 r0 = make_float2(acc[i][j][0] * alpha, acc[i][j][1] * alpha);
            float2 r1 = make_float2(acc[i][j][2] * alpha, acc[i][j][3] * alpha);
            if (bias) {
                float bx = bias[n0], by = bias[n0 + 1];
                r0.x += bx; r0.y += by; r1.x += bx; r1.y += by;
            }
            float2* p0 = (float2*)&C[(long long)m0 * ldc + n0];
            float2* p1 = (float2*)&C[(long long)(m0 + 8) * ldc + n0];
            if (accum) {
                float2 o0 = *p0, o1 = *p1;
                r0.x += o0.x; r0.y += o0.y; r1.x += o1.x; r1.y += o1.y;
            }
            *p0 = r0;
            *p1 = r1;
        }
    }
}

// ---------------- elementwise ----------------
__global__ void mean2_kernel(const float* __restrict__ a, const float* __restrict__ b,
                             float* __restrict__ o, int n)
{
    int i = blockIdx.x * blockDim.x + threadIdx.x;
    if (i < n) o[i] = 0.5f * (a[i] + b[i]);
}

__global__ void final_gate_kernel(const float* __restrict__ o, const float* __restrict__ rec,
                                  const float* __restrict__ gpre, float* __restrict__ outp, int n)
{
    int i = blockIdx.x * blockDim.x + threadIdx.x;
    if (i < n) {
        float s = 1.0f / (1.0f + __expf(-gpre[i]));
        outp[i] = o[i] * (1.0f - s) + rec[i] * s;
    }
}

// ---------------- host launch ----------------
extern "C" void kernel_launch(void* const* d_in, const int* in_sizes, int n_in,
                              void* d_out, int out_size)
{
    const float* hs   = (const float*)d_in[0];
    const float* past = (const float*)d_in[1];
    const float* Wq = (const float*)d_in[2],  *bq = (const float*)d_in[3];
    const float* Wk = (const float*)d_in[4],  *bk = (const float*)d_in[5];
    const float* Wv = (const float*)d_in[6],  *bv = (const float*)d_in[7];
    const float* Wo = (const float*)d_in[8],  *bo = (const float*)d_in[9];
    const float* Wrq = (const float*)d_in[10], *brq = (const float*)d_in[11];
    const float* Wrk = (const float*)d_in[12], *brk = (const float*)d_in[13];
    const float* Wrv = (const float*)d_in[14], *brv = (const float*)d_in[15];
    const float* Wg = (const float*)d_in[16],  *bg = (const float*)d_in[17];
    float* outp = (float*)d_out;

    static int smem_set = 0;
    if (!smem_set) {
        cudaFuncSetAttribute(flash_kernel, cudaFuncAttributeMaxDynamicSharedMemorySize, FLASH_SMEM);
        smem_set = 1;
    }

    float *q, *k, *v, *ctx, *out, *rq, *rk, *rv, *rctx0, *rctx1, *rec, *gate;
    cudaGetSymbolAddress((void**)&q,      g_q);
    cudaGetSymbolAddress((void**)&k,      g_k);
    cudaGetSymbolAddress((void**)&v,      g_v);
    cudaGetSymbolAddress((void**)&ctx,    g_ctx);
    cudaGetSymbolAddress((void**)&out,    g_out);
    cudaGetSymbolAddress((void**)&rq,     g_rq);
    cudaGetSymbolAddress((void**)&rk,     g_rk);
    cudaGetSymbolAddress((void**)&rv,     g_rv);
    cudaGetSymbolAddress((void**)&rctx0,  g_rctx0);
    cudaGetSymbolAddress((void**)&rctx1,  g_rctx1);
    cudaGetSymbolAddress((void**)&rec,    g_rec);
    cudaGetSymbolAddress((void**)&gate,   g_gate);

    const dim3 blk(256);
    const int nElem = SEQ * HID;
    const dim3 egrid((nElem + 255) / 256);
    const dim3 gDense(HID / 128, SEQ / 128);
    const dim3 gFlash(SEQ / 128, NHEAD);

    #define DENSE mma_gemm<128,128,32,32,64>

    // ---- Q/K/V projections ----
    DENSE<<<gDense, blk>>>(hs, HID, Wq, HID, bq, q, HID, HID, 1.0f, 0);
    DENSE<<<gDense, blk>>>(hs, HID, Wk, HID, bk, k, HID, HID, 1.0f, 0);
    DENSE<<<gDense, blk>>>(hs, HID, Wv, HID, bv, v, HID, HID, 1.0f, 0);

    // ---- self attention (fused) ----
    flash_kernel<<<gFlash, blk, FLASH_SMEM>>>(q, k, v, ctx);
    DENSE<<<gDense, blk>>>(ctx, HID, Wo, HID, bo, out, HID, HID, 1.0f, 0);

    // ---- recursive attention over P=2 past states ----
    DENSE<<<gDense, blk>>>(out, HID, Wrq, HID, brq, rq, HID, HID, 1.0f, 0);

    float* rctx_dst[2] = {rctx0, rctx1};
    for (int p = 0; p < 2; p++) {
        const float* pastp = past + (long long)p * SEQ * HID;
        DENSE<<<gDense, blk>>>(pastp, HID, Wrk, HID, brk, rk, HID, HID, 1.0f, 0);
        DENSE<<<gDense, blk>>>(pastp, HID, Wrv, HID, brv, rv, HID, HID, 1.0f, 0);
        flash_kernel<<<gFlash, blk, FLASH_SMEM>>>(rq, rk, rv, rctx_dst[p]);
    }
    mean2_kernel<<<egrid, blk>>>(rctx0, rctx1, rec, nElem);

    // ---- gate = sigmoid([out, rec] @ Wg + bg); blend ----
    DENSE<<<gDense, blk>>>(out, HID, Wg, HID, bg, gate, HID, HID, 1.0f, 0);
    DENSE<<<gDense, blk>>>(rec, HID, Wg + (long long)HID * HID, HID, nullptr, gate, HID, HID, 1.0f, 1);
    final_gate_kernel<<<egrid, blk>>>(out, rec, gate, outp, nElem);
}